// round 1
// baseline (speedup 1.0000x reference)
#include <cuda_runtime.h>
#include <math.h>

#define BATCH 4
#define SEQ   2048
#define DIM   2048
#define NH    16
#define DHEAD 128

// Scratch (allocation-free rule: __device__ globals)
__device__ float g_Q[BATCH * SEQ * DIM];
__device__ float g_K[BATCH * SEQ * DIM];
__device__ float g_V[BATCH * SEQ * DIM];
__device__ float g_A[BATCH * SEQ * DIM];

// ---------------------------------------------------------------------------
// NT GEMM: C[m,n] = (sum_k A[m,k] * W[n,k] + bias[n]) * gate(n)
// gate: mode 0 -> 1, mode 1 -> cos(rot[n]), mode 2 -> sin(rot[n])
// Tiles: 128x128x16, 256 threads, 8x8 register micro-tile.
// ---------------------------------------------------------------------------
__global__ __launch_bounds__(256) void gemm_nt_kernel(
    const float* __restrict__ A, const float* __restrict__ W,
    const float* __restrict__ bias, const float* __restrict__ rot,
    int mode, float* __restrict__ C, int M, int N, int K)
{
    __shared__ float As[16][128];
    __shared__ float Ws[16][128];

    const int tid = threadIdx.x;
    const int bm = blockIdx.y * 128;
    const int bn = blockIdx.x * 128;
    const int tr = tid >> 4;          // 0..15 (row group)
    const int tc = tid & 15;          // 0..15 (col group)
    const int lr = tid >> 2;          // 0..63 load row
    const int lc = (tid & 3) << 2;    // 0,4,8,12 load k-offset

    float acc[8][8];
#pragma unroll
    for (int i = 0; i < 8; i++)
#pragma unroll
        for (int j = 0; j < 8; j++) acc[i][j] = 0.f;

    const float* Ag = A + (size_t)(bm + lr) * K + lc;
    const float* Wg = W + (size_t)(bn + lr) * K + lc;

    for (int k0 = 0; k0 < K; k0 += 16) {
#pragma unroll
        for (int hh = 0; hh < 2; hh++) {
            float4 a = *(const float4*)(Ag + (size_t)hh * 64 * K + k0);
            As[lc + 0][lr + hh * 64] = a.x;
            As[lc + 1][lr + hh * 64] = a.y;
            As[lc + 2][lr + hh * 64] = a.z;
            As[lc + 3][lr + hh * 64] = a.w;
            float4 w = *(const float4*)(Wg + (size_t)hh * 64 * K + k0);
            Ws[lc + 0][lr + hh * 64] = w.x;
            Ws[lc + 1][lr + hh * 64] = w.y;
            Ws[lc + 2][lr + hh * 64] = w.z;
            Ws[lc + 3][lr + hh * 64] = w.w;
        }
        __syncthreads();
#pragma unroll
        for (int k = 0; k < 16; k++) {
            float af[8], wf[8];
            *(float4*)(af)     = *(const float4*)(&As[k][tr * 8]);
            *(float4*)(af + 4) = *(const float4*)(&As[k][tr * 8 + 4]);
            *(float4*)(wf)     = *(const float4*)(&Ws[k][tc * 8]);
            *(float4*)(wf + 4) = *(const float4*)(&Ws[k][tc * 8 + 4]);
#pragma unroll
            for (int i = 0; i < 8; i++)
#pragma unroll
                for (int j = 0; j < 8; j++)
                    acc[i][j] += af[i] * wf[j];
        }
        __syncthreads();
    }

    // epilogue: bias + optional cos/sin gate, vectorized stores
    float cb[8], cs[8];
#pragma unroll
    for (int j = 0; j < 8; j++) {
        int col = bn + tc * 8 + j;
        cb[j] = bias[col];
        float s = 1.f;
        if (mode == 1) s = cosf(rot[col]);
        else if (mode == 2) s = sinf(rot[col]);
        cs[j] = s;
    }
#pragma unroll
    for (int i = 0; i < 8; i++) {
        int row = bm + tr * 8 + i;
        float o[8];
#pragma unroll
        for (int j = 0; j < 8; j++) o[j] = (acc[i][j] + cb[j]) * cs[j];
        *(float4*)(C + (size_t)row * N + bn + tc * 8)     = *(float4*)(o);
        *(float4*)(C + (size_t)row * N + bn + tc * 8 + 4) = *(float4*)(o + 4);
    }
}

// ---------------------------------------------------------------------------
// Flash attention, fp32, BM=64 query rows, BN=64 key rows, DH=128.
// Layout of Q/K/V/O: (b, s, h, dh) flattened == (b, s, d).
// ---------------------------------------------------------------------------
#define FLASH_SMEM_FLOATS (3 * 64 * 128 + 64 * 65 + 3 * 64)

__global__ __launch_bounds__(256) void flash_kernel(
    const float* __restrict__ Q, const float* __restrict__ K,
    const float* __restrict__ V, const float* __restrict__ spiral,
    float* __restrict__ O)
{
    extern __shared__ float fs[];
    float* sQ  = fs;                    // 64*128
    float* sK  = sQ + 64 * 128;         // 64*128
    float* sV  = sK + 64 * 128;         // 64*128
    float* sS  = sV + 64 * 128;         // 64*65 (padded)
    float* sM  = sS + 64 * 65;          // 64
    float* sL  = sM + 64;               // 64
    float* sAl = sL + 64;               // 64

    const int tid = threadIdx.x;
    const int qt = blockIdx.x, h = blockIdx.y, b = blockIdx.z;
    const int s0 = qt * 64;
    const float scale = spiral[h] * 0.08838834764831845f; // 1/sqrt(128)

    const size_t baseQ = ((size_t)b * SEQ + s0) * DIM + (size_t)h * DHEAD;
    const size_t baseK = (size_t)b * SEQ * DIM + (size_t)h * DHEAD;

    // load Q tile (coalesced float4)
    for (int idx = tid; idx < 64 * 32; idx += 256) {
        int r = idx >> 5, c4 = (idx & 31) << 2;
        *(float4*)(sQ + r * 128 + c4) =
            *(const float4*)(Q + baseQ + (size_t)r * DIM + c4);
    }
    if (tid < 64) { sM[tid] = -INFINITY; sL[tid] = 0.f; }

    const int warp = tid >> 5, lane = tid & 31;
    const int ty = tid >> 4, tx = tid & 15;

    float4 o[8];
#pragma unroll
    for (int i = 0; i < 8; i++) o[i] = make_float4(0.f, 0.f, 0.f, 0.f);

    for (int kt = 0; kt < SEQ / 64; kt++) {
        __syncthreads();
        const size_t kb = baseK + (size_t)kt * 64 * DIM;
        for (int idx = tid; idx < 64 * 32; idx += 256) {
            int r = idx >> 5, c4 = (idx & 31) << 2;
            *(float4*)(sK + r * 128 + c4) =
                *(const float4*)(K + kb + (size_t)r * DIM + c4);
            *(float4*)(sV + r * 128 + c4) =
                *(const float4*)(V + kb + (size_t)r * DIM + c4);
        }
        __syncthreads();

        // ---- scores: 64x64, thread computes 4x4 micro-tile ----
        float sc[4][4];
#pragma unroll
        for (int i = 0; i < 4; i++)
#pragma unroll
            for (int j = 0; j < 4; j++) sc[i][j] = 0.f;

#pragma unroll 4
        for (int c4 = 0; c4 < 128; c4 += 4) {
            float4 qf[4], kf[4];
#pragma unroll
            for (int i = 0; i < 4; i++)
                qf[i] = *(const float4*)(sQ + (ty * 4 + i) * 128 + c4);
#pragma unroll
            for (int j = 0; j < 4; j++)
                kf[j] = *(const float4*)(sK + (tx * 4 + j) * 128 + c4);
#pragma unroll
            for (int i = 0; i < 4; i++)
#pragma unroll
                for (int j = 0; j < 4; j++)
                    sc[i][j] += qf[i].x * kf[j].x + qf[i].y * kf[j].y +
                                qf[i].z * kf[j].z + qf[i].w * kf[j].w;
        }
#pragma unroll
        for (int i = 0; i < 4; i++)
#pragma unroll
            for (int j = 0; j < 4; j++)
                sS[(ty * 4 + i) * 65 + tx * 4 + j] = sc[i][j] * scale;
        __syncthreads();

        // ---- online softmax: 4 threads per row, 16 cols each ----
        {
            const int r = tid >> 2, g = tid & 3;
            float vals[16];
            float mx = -INFINITY;
#pragma unroll
            for (int jj = 0; jj < 16; jj++) {
                vals[jj] = sS[r * 65 + g * 16 + jj];
                mx = fmaxf(mx, vals[jj]);
            }
            mx = fmaxf(mx, __shfl_xor_sync(0xffffffffu, mx, 1));
            mx = fmaxf(mx, __shfl_xor_sync(0xffffffffu, mx, 2));
            float mo = sM[r];
            float mn = fmaxf(mo, mx);
            float sum = 0.f;
#pragma unroll
            for (int jj = 0; jj < 16; jj++) {
                float p = __expf(vals[jj] - mn);
                sS[r * 65 + g * 16 + jj] = p;
                sum += p;
            }
            sum += __shfl_xor_sync(0xffffffffu, sum, 1);
            sum += __shfl_xor_sync(0xffffffffu, sum, 2);
            if (g == 0) {
                float al = __expf(mo - mn);   // 0 on first tile (mo = -inf)
                sAl[r] = al;
                sL[r] = sL[r] * al + sum;
                sM[r] = mn;
            }
        }
        __syncthreads();

        // ---- O = O*alpha + P @ V ; warp w owns rows w*8..w*8+7, lane owns cols lane*4..+3
#pragma unroll
        for (int i = 0; i < 8; i++) {
            float al = sAl[warp * 8 + i];
            o[i].x *= al; o[i].y *= al; o[i].z *= al; o[i].w *= al;
        }
        for (int n = 0; n < 64; n++) {
            float4 v = *(const float4*)(sV + n * 128 + lane * 4);
#pragma unroll
            for (int i = 0; i < 8; i++) {
                float p = sS[(warp * 8 + i) * 65 + n];
                o[i].x += p * v.x; o[i].y += p * v.y;
                o[i].z += p * v.z; o[i].w += p * v.w;
            }
        }
    }

    // finalize + store
#pragma unroll
    for (int i = 0; i < 8; i++) {
        int r = warp * 8 + i;
        float inv = 1.0f / sL[r];
        float4 ov = make_float4(o[i].x * inv, o[i].y * inv, o[i].z * inv, o[i].w * inv);
        *(float4*)(O + baseQ + (size_t)r * DIM + lane * 4) = ov;
    }
}

// ---------------------------------------------------------------------------
extern "C" void kernel_launch(void* const* d_in, const int* in_sizes, int n_in,
                              void* d_out, int out_size)
{
    const float* x      = (const float*)d_in[0];
    const float* Wq     = (const float*)d_in[1];
    const float* bq     = (const float*)d_in[2];
    const float* Wk     = (const float*)d_in[3];
    const float* bk     = (const float*)d_in[4];
    const float* Wv     = (const float*)d_in[5];
    const float* bv     = (const float*)d_in[6];
    const float* Wo     = (const float*)d_in[7];
    const float* bo     = (const float*)d_in[8];
    const float* spiral = (const float*)d_in[9];
    const float* rot    = (const float*)d_in[10];
    float* out = (float*)d_out;

    float *Qp, *Kp, *Vp, *Ap;
    cudaGetSymbolAddress((void**)&Qp, g_Q);
    cudaGetSymbolAddress((void**)&Kp, g_K);
    cudaGetSymbolAddress((void**)&Vp, g_V);
    cudaGetSymbolAddress((void**)&Ap, g_A);

    const int M = BATCH * SEQ;                  // 8192
    dim3 gg(DIM / 128, M / 128);                // 16 x 64
    gemm_nt_kernel<<<gg, 256>>>(x, Wq, bq, rot, 1, Qp, M, DIM, DIM);  // * cos
    gemm_nt_kernel<<<gg, 256>>>(x, Wk, bk, rot, 2, Kp, M, DIM, DIM);  // * sin
    gemm_nt_kernel<<<gg, 256>>>(x, Wv, bv, nullptr, 0, Vp, M, DIM, DIM);

    const int smem = FLASH_SMEM_FLOATS * (int)sizeof(float);
    cudaFuncSetAttribute(flash_kernel, cudaFuncAttributeMaxDynamicSharedMemorySize, smem);
    flash_kernel<<<dim3(SEQ / 64, NH, BATCH), 256, smem>>>(Qp, Kp, Vp, spiral, Ap);

    gemm_nt_kernel<<<gg, 256>>>(Ap, Wo, bo, nullptr, 0, out, M, DIM, DIM);
}

// round 2
// speedup vs baseline: 1.3980x; 1.3980x over previous
#include <cuda_runtime.h>
#include <math.h>

#define BATCH 4
#define SEQ   2048
#define DIM   2048
#define NH    16
#define DHEAD 128

// Scratch (allocation-free rule: __device__ globals)
__device__ float g_Q[BATCH * SEQ * DIM];
__device__ float g_K[BATCH * SEQ * DIM];
__device__ float g_V[BATCH * SEQ * DIM];
__device__ float g_A[BATCH * SEQ * DIM];

// ---------------------------------------------------------------------------
// TF32 tensor-core NT GEMM: C[m,n] = (sum_k A[m,k]*W[n,k] + bias[n]) * gate(n)
// gate: mode 0 -> 1, mode 1 -> cos(rot[n]), mode 2 -> sin(rot[n])
// CTA tile 128x128x32, 256 threads (8 warps, each 64x32), mma.m16n8k8.tf32.
// ---------------------------------------------------------------------------
#define GBM 128
#define GBN 128
#define GBK 32
#define GSTRIDE 36                       // 32 + 4 pad -> conflict-free frags
#define GBUF (128 * GSTRIDE)             // elems per tile buffer
#define GEMM_SMEM_BYTES (4 * GBUF * 4)   // A[2] + B[2], 73728 B

__device__ __forceinline__ unsigned f2tf32(float x) {
    unsigned u;
    asm("cvt.rna.tf32.f32 %0, %1;" : "=r"(u) : "f"(x));
    return u;
}

__device__ __forceinline__ void mma_tf32(float* d, const unsigned* a, const unsigned* b) {
    asm volatile(
        "mma.sync.aligned.m16n8k8.row.col.f32.tf32.tf32.f32 "
        "{%0,%1,%2,%3}, {%4,%5,%6,%7}, {%8,%9}, {%0,%1,%2,%3};\n"
        : "+f"(d[0]), "+f"(d[1]), "+f"(d[2]), "+f"(d[3])
        : "r"(a[0]), "r"(a[1]), "r"(a[2]), "r"(a[3]), "r"(b[0]), "r"(b[1]));
}

__global__ __launch_bounds__(256) void gemm_tf32_kernel(
    const float* __restrict__ A, const float* __restrict__ W,
    const float* __restrict__ bias, const float* __restrict__ rot,
    int mode, float* __restrict__ C, int M, int N, int K)
{
    extern __shared__ unsigned sm[];
    unsigned* As = sm;                 // [2][128][GSTRIDE]
    unsigned* Bs = sm + 2 * GBUF;      // [2][128][GSTRIDE]

    const int tid = threadIdx.x;
    const int warp = tid >> 5, lane = tid & 31;
    const int wm = (warp >> 2) * 64;   // 0 / 64
    const int wn = (warp & 3) * 32;    // 0..96
    const int bm = blockIdx.y * GBM, bn = blockIdx.x * GBN;

    const int lrow = tid >> 3;          // 0..31
    const int lcol = (tid & 7) * 4;     // 0..28

    float acc[4][4][4];
#pragma unroll
    for (int i = 0; i < 4; i++)
#pragma unroll
        for (int j = 0; j < 4; j++)
#pragma unroll
            for (int t = 0; t < 4; t++) acc[i][j][t] = 0.f;

    const float* Ag = A + (size_t)(bm + lrow) * K + lcol;
    const float* Wg = W + (size_t)(bn + lrow) * K + lcol;

    float4 ra[4], rb[4];

    auto G2R = [&](int kt) {
        const size_t ko = (size_t)kt * GBK;
#pragma unroll
        for (int it = 0; it < 4; it++) {
            ra[it] = *(const float4*)(Ag + (size_t)it * 32 * K + ko);
            rb[it] = *(const float4*)(Wg + (size_t)it * 32 * K + ko);
        }
    };
    auto R2S = [&](int buf) {
#pragma unroll
        for (int it = 0; it < 4; it++) {
            int base = buf * GBUF + (lrow + it * 32) * GSTRIDE + lcol;
            uint4 ua = make_uint4(f2tf32(ra[it].x), f2tf32(ra[it].y),
                                  f2tf32(ra[it].z), f2tf32(ra[it].w));
            uint4 ub = make_uint4(f2tf32(rb[it].x), f2tf32(rb[it].y),
                                  f2tf32(rb[it].z), f2tf32(rb[it].w));
            *(uint4*)(As + base) = ua;
            *(uint4*)(Bs + base) = ub;
        }
    };

    const int ntiles = K / GBK;   // 64
    G2R(0);
    R2S(0);
    __syncthreads();

    const int lq = lane >> 2;     // lane/4
    const int lr = lane & 3;      // lane%4

    for (int kt = 0; kt < ntiles; kt++) {
        if (kt + 1 < ntiles) G2R(kt + 1);

        const unsigned* Ab = As + (kt & 1) * GBUF;
        const unsigned* Bb = Bs + (kt & 1) * GBUF;
#pragma unroll
        for (int k8 = 0; k8 < 4; k8++) {
            const int kc = k8 * 8 + lr;
            unsigned af[4][4], bf[4][2];
#pragma unroll
            for (int i = 0; i < 4; i++) {
                int r = wm + i * 16 + lq;
                af[i][0] = Ab[r * GSTRIDE + kc];
                af[i][1] = Ab[(r + 8) * GSTRIDE + kc];
                af[i][2] = Ab[r * GSTRIDE + kc + 4];
                af[i][3] = Ab[(r + 8) * GSTRIDE + kc + 4];
            }
#pragma unroll
            for (int j = 0; j < 4; j++) {
                int c = wn + j * 8 + lq;
                bf[j][0] = Bb[c * GSTRIDE + kc];
                bf[j][1] = Bb[c * GSTRIDE + kc + 4];
            }
#pragma unroll
            for (int i = 0; i < 4; i++)
#pragma unroll
                for (int j = 0; j < 4; j++)
                    mma_tf32(acc[i][j], af[i], bf[j]);
        }

        if (kt + 1 < ntiles) R2S((kt + 1) & 1);
        __syncthreads();
    }

    // epilogue: bias + optional cos/sin gate
#pragma unroll
    for (int j = 0; j < 4; j++) {
        int c0 = bn + wn + j * 8 + (lr << 1);
        float b0 = __ldg(bias + c0), b1 = __ldg(bias + c0 + 1);
        float g0 = 1.f, g1 = 1.f;
        if (mode == 1) { g0 = cosf(__ldg(rot + c0)); g1 = cosf(__ldg(rot + c0 + 1)); }
        else if (mode == 2) { g0 = sinf(__ldg(rot + c0)); g1 = sinf(__ldg(rot + c0 + 1)); }
#pragma unroll
        for (int i = 0; i < 4; i++) {
            int r0 = bm + wm + i * 16 + lq;
            float2 v0 = make_float2((acc[i][j][0] + b0) * g0, (acc[i][j][1] + b1) * g1);
            float2 v1 = make_float2((acc[i][j][2] + b0) * g0, (acc[i][j][3] + b1) * g1);
            *(float2*)(C + (size_t)r0 * N + c0)       = v0;
            *(float2*)(C + (size_t)(r0 + 8) * N + c0) = v1;
        }
    }
}

// ---------------------------------------------------------------------------
// Flash attention, fp32, BM=64 query rows, BN=64 key rows, DH=128.
// ---------------------------------------------------------------------------
#define FLASH_SMEM_FLOATS (3 * 64 * 128 + 64 * 65 + 3 * 64)

__global__ __launch_bounds__(256) void flash_kernel(
    const float* __restrict__ Q, const float* __restrict__ K,
    const float* __restrict__ V, const float* __restrict__ spiral,
    float* __restrict__ O)
{
    extern __shared__ float fs[];
    float* sQ  = fs;
    float* sK  = sQ + 64 * 128;
    float* sV  = sK + 64 * 128;
    float* sS  = sV + 64 * 128;
    float* sM  = sS + 64 * 65;
    float* sL  = sM + 64;
    float* sAl = sL + 64;

    const int tid = threadIdx.x;
    const int qt = blockIdx.x, h = blockIdx.y, b = blockIdx.z;
    const int s0 = qt * 64;
    const float scale = spiral[h] * 0.08838834764831845f;

    const size_t baseQ = ((size_t)b * SEQ + s0) * DIM + (size_t)h * DHEAD;
    const size_t baseK = (size_t)b * SEQ * DIM + (size_t)h * DHEAD;

    for (int idx = tid; idx < 64 * 32; idx += 256) {
        int r = idx >> 5, c4 = (idx & 31) << 2;
        *(float4*)(sQ + r * 128 + c4) =
            *(const float4*)(Q + baseQ + (size_t)r * DIM + c4);
    }
    if (tid < 64) { sM[tid] = -INFINITY; sL[tid] = 0.f; }

    const int warp = tid >> 5, lane = tid & 31;
    const int ty = tid >> 4, tx = tid & 15;

    float4 o[8];
#pragma unroll
    for (int i = 0; i < 8; i++) o[i] = make_float4(0.f, 0.f, 0.f, 0.f);

    for (int kt = 0; kt < SEQ / 64; kt++) {
        __syncthreads();
        const size_t kb = baseK + (size_t)kt * 64 * DIM;
        for (int idx = tid; idx < 64 * 32; idx += 256) {
            int r = idx >> 5, c4 = (idx & 31) << 2;
            *(float4*)(sK + r * 128 + c4) =
                *(const float4*)(K + kb + (size_t)r * DIM + c4);
            *(float4*)(sV + r * 128 + c4) =
                *(const float4*)(V + kb + (size_t)r * DIM + c4);
        }
        __syncthreads();

        float sc[4][4];
#pragma unroll
        for (int i = 0; i < 4; i++)
#pragma unroll
            for (int j = 0; j < 4; j++) sc[i][j] = 0.f;

#pragma unroll 4
        for (int c4 = 0; c4 < 128; c4 += 4) {
            float4 qf[4], kf[4];
#pragma unroll
            for (int i = 0; i < 4; i++)
                qf[i] = *(const float4*)(sQ + (ty * 4 + i) * 128 + c4);
#pragma unroll
            for (int j = 0; j < 4; j++)
                kf[j] = *(const float4*)(sK + (tx * 4 + j) * 128 + c4);
#pragma unroll
            for (int i = 0; i < 4; i++)
#pragma unroll
                for (int j = 0; j < 4; j++)
                    sc[i][j] += qf[i].x * kf[j].x + qf[i].y * kf[j].y +
                                qf[i].z * kf[j].z + qf[i].w * kf[j].w;
        }
#pragma unroll
        for (int i = 0; i < 4; i++)
#pragma unroll
            for (int j = 0; j < 4; j++)
                sS[(ty * 4 + i) * 65 + tx * 4 + j] = sc[i][j] * scale;
        __syncthreads();

        {
            const int r = tid >> 2, g = tid & 3;
            float vals[16];
            float mx = -INFINITY;
#pragma unroll
            for (int jj = 0; jj < 16; jj++) {
                vals[jj] = sS[r * 65 + g * 16 + jj];
                mx = fmaxf(mx, vals[jj]);
            }
            mx = fmaxf(mx, __shfl_xor_sync(0xffffffffu, mx, 1));
            mx = fmaxf(mx, __shfl_xor_sync(0xffffffffu, mx, 2));
            float mo = sM[r];
            float mn = fmaxf(mo, mx);
            float sum = 0.f;
#pragma unroll
            for (int jj = 0; jj < 16; jj++) {
                float p = __expf(vals[jj] - mn);
                sS[r * 65 + g * 16 + jj] = p;
                sum += p;
            }
            sum += __shfl_xor_sync(0xffffffffu, sum, 1);
            sum += __shfl_xor_sync(0xffffffffu, sum, 2);
            if (g == 0) {
                float al = __expf(mo - mn);
                sAl[r] = al;
                sL[r] = sL[r] * al + sum;
                sM[r] = mn;
            }
        }
        __syncthreads();

#pragma unroll
        for (int i = 0; i < 8; i++) {
            float al = sAl[warp * 8 + i];
            o[i].x *= al; o[i].y *= al; o[i].z *= al; o[i].w *= al;
        }
        for (int n = 0; n < 64; n++) {
            float4 v = *(const float4*)(sV + n * 128 + lane * 4);
#pragma unroll
            for (int i = 0; i < 8; i++) {
                float p = sS[(warp * 8 + i) * 65 + n];
                o[i].x += p * v.x; o[i].y += p * v.y;
                o[i].z += p * v.z; o[i].w += p * v.w;
            }
        }
    }

#pragma unroll
    for (int i = 0; i < 8; i++) {
        int r = warp * 8 + i;
        float inv = 1.0f / sL[r];
        float4 ov = make_float4(o[i].x * inv, o[i].y * inv, o[i].z * inv, o[i].w * inv);
        *(float4*)(O + baseQ + (size_t)r * DIM + lane * 4) = ov;
    }
}

// ---------------------------------------------------------------------------
extern "C" void kernel_launch(void* const* d_in, const int* in_sizes, int n_in,
                              void* d_out, int out_size)
{
    const float* x      = (const float*)d_in[0];
    const float* Wq     = (const float*)d_in[1];
    const float* bq     = (const float*)d_in[2];
    const float* Wk     = (const float*)d_in[3];
    const float* bk     = (const float*)d_in[4];
    const float* Wv     = (const float*)d_in[5];
    const float* bv     = (const float*)d_in[6];
    const float* Wo     = (const float*)d_in[7];
    const float* bo     = (const float*)d_in[8];
    const float* spiral = (const float*)d_in[9];
    const float* rot    = (const float*)d_in[10];
    float* out = (float*)d_out;

    float *Qp, *Kp, *Vp, *Ap;
    cudaGetSymbolAddress((void**)&Qp, g_Q);
    cudaGetSymbolAddress((void**)&Kp, g_K);
    cudaGetSymbolAddress((void**)&Vp, g_V);
    cudaGetSymbolAddress((void**)&Ap, g_A);

    const int M = BATCH * SEQ;                  // 8192
    dim3 gg(DIM / GBN, M / GBM);                // 16 x 64

    cudaFuncSetAttribute(gemm_tf32_kernel,
                         cudaFuncAttributeMaxDynamicSharedMemorySize, GEMM_SMEM_BYTES);

    gemm_tf32_kernel<<<gg, 256, GEMM_SMEM_BYTES>>>(x, Wq, bq, rot, 1, Qp, M, DIM, DIM);
    gemm_tf32_kernel<<<gg, 256, GEMM_SMEM_BYTES>>>(x, Wk, bk, rot, 2, Kp, M, DIM, DIM);
    gemm_tf32_kernel<<<gg, 256, GEMM_SMEM_BYTES>>>(x, Wv, bv, nullptr, 0, Vp, M, DIM, DIM);

    const int fsmem = FLASH_SMEM_FLOATS * (int)sizeof(float);
    cudaFuncSetAttribute(flash_kernel, cudaFuncAttributeMaxDynamicSharedMemorySize, fsmem);
    flash_kernel<<<dim3(SEQ / 64, NH, BATCH), 256, fsmem>>>(Qp, Kp, Vp, spiral, Ap);

    gemm_tf32_kernel<<<gg, 256, GEMM_SMEM_BYTES>>>(Ap, Wo, bo, nullptr, 0, out, M, DIM, DIM);
}

// round 5
// speedup vs baseline: 5.3213x; 3.8063x over previous
#include <cuda_runtime.h>
#include <math.h>

#define BATCH 4
#define SEQ   2048
#define DIM   2048
#define NH    16
#define DHEAD 128

__device__ float g_Q[BATCH * SEQ * DIM];
__device__ float g_K[BATCH * SEQ * DIM];
__device__ float g_V[BATCH * SEQ * DIM];
__device__ float g_A[BATCH * SEQ * DIM];

__device__ __forceinline__ unsigned f2tf32(float x) {
    unsigned u;
    asm("cvt.rna.tf32.f32 %0, %1;" : "=r"(u) : "f"(x));
    return u;
}

__device__ __forceinline__ void mma_tf32(float* d, const unsigned* a, const unsigned* b) {
    asm volatile(
        "mma.sync.aligned.m16n8k8.row.col.f32.tf32.tf32.f32 "
        "{%0,%1,%2,%3}, {%4,%5,%6,%7}, {%8,%9}, {%0,%1,%2,%3};\n"
        : "+f"(d[0]), "+f"(d[1]), "+f"(d[2]), "+f"(d[3])
        : "r"(a[0]), "r"(a[1]), "r"(a[2]), "r"(a[3]), "r"(b[0]), "r"(b[1]));
}

// ---------------------------------------------------------------------------
// TF32 NT GEMM: C = (A @ W^T + bias) * gate, optional tf32 rounding of output
// ---------------------------------------------------------------------------
#define GBM 128
#define GBN 128
#define GBK 32
#define GSTRIDE 36
#define GBUF (128 * GSTRIDE)
#define GEMM_SMEM_BYTES (4 * GBUF * 4)

__global__ __launch_bounds__(256) void gemm_tf32_kernel(
    const float* __restrict__ A, const float* __restrict__ W,
    const float* __restrict__ bias, const float* __restrict__ rot,
    int mode, int roundout, float* __restrict__ C, int M, int N, int K)
{
    extern __shared__ unsigned sm[];
    unsigned* As = sm;
    unsigned* Bs = sm + 2 * GBUF;

    const int tid = threadIdx.x;
    const int warp = tid >> 5, lane = tid & 31;
    const int wm = (warp >> 2) * 64;
    const int wn = (warp & 3) * 32;
    const int bm = blockIdx.y * GBM, bn = blockIdx.x * GBN;

    const int lrow = tid >> 3;
    const int lcol = (tid & 7) * 4;

    float acc[4][4][4];
#pragma unroll
    for (int i = 0; i < 4; i++)
#pragma unroll
        for (int j = 0; j < 4; j++)
#pragma unroll
            for (int t = 0; t < 4; t++) acc[i][j][t] = 0.f;

    const float* Ag = A + (size_t)(bm + lrow) * K + lcol;
    const float* Wg = W + (size_t)(bn + lrow) * K + lcol;

    float4 ra[4], rb[4];

    auto G2R = [&](int kt) {
        const size_t ko = (size_t)kt * GBK;
#pragma unroll
        for (int it = 0; it < 4; it++) {
            ra[it] = *(const float4*)(Ag + (size_t)it * 32 * K + ko);
            rb[it] = *(const float4*)(Wg + (size_t)it * 32 * K + ko);
        }
    };
    auto R2S = [&](int buf) {
#pragma unroll
        for (int it = 0; it < 4; it++) {
            int base = buf * GBUF + (lrow + it * 32) * GSTRIDE + lcol;
            uint4 ua = make_uint4(f2tf32(ra[it].x), f2tf32(ra[it].y),
                                  f2tf32(ra[it].z), f2tf32(ra[it].w));
            uint4 ub = make_uint4(f2tf32(rb[it].x), f2tf32(rb[it].y),
                                  f2tf32(rb[it].z), f2tf32(rb[it].w));
            *(uint4*)(As + base) = ua;
            *(uint4*)(Bs + base) = ub;
        }
    };

    const int ntiles = K / GBK;
    G2R(0);
    R2S(0);
    __syncthreads();

    const int lq = lane >> 2;
    const int lr = lane & 3;

    for (int kt = 0; kt < ntiles; kt++) {
        if (kt + 1 < ntiles) G2R(kt + 1);

        const unsigned* Ab = As + (kt & 1) * GBUF;
        const unsigned* Bb = Bs + (kt & 1) * GBUF;
#pragma unroll
        for (int k8 = 0; k8 < 4; k8++) {
            const int kc = k8 * 8 + lr;
            unsigned af[4][4], bf[4][2];
#pragma unroll
            for (int i = 0; i < 4; i++) {
                int r = wm + i * 16 + lq;
                af[i][0] = Ab[r * GSTRIDE + kc];
                af[i][1] = Ab[(r + 8) * GSTRIDE + kc];
                af[i][2] = Ab[r * GSTRIDE + kc + 4];
                af[i][3] = Ab[(r + 8) * GSTRIDE + kc + 4];
            }
#pragma unroll
            for (int j = 0; j < 4; j++) {
                int c = wn + j * 8 + lq;
                bf[j][0] = Bb[c * GSTRIDE + kc];
                bf[j][1] = Bb[c * GSTRIDE + kc + 4];
            }
#pragma unroll
            for (int i = 0; i < 4; i++)
#pragma unroll
                for (int j = 0; j < 4; j++)
                    mma_tf32(acc[i][j], af[i], bf[j]);
        }

        if (kt + 1 < ntiles) R2S((kt + 1) & 1);
        __syncthreads();
    }

#pragma unroll
    for (int j = 0; j < 4; j++) {
        int c0 = bn + wn + j * 8 + (lr << 1);
        float b0 = __ldg(bias + c0), b1 = __ldg(bias + c0 + 1);
        float g0 = 1.f, g1 = 1.f;
        if (mode == 1) { g0 = cosf(__ldg(rot + c0)); g1 = cosf(__ldg(rot + c0 + 1)); }
        else if (mode == 2) { g0 = sinf(__ldg(rot + c0)); g1 = sinf(__ldg(rot + c0 + 1)); }
#pragma unroll
        for (int i = 0; i < 4; i++) {
            int r0 = bm + wm + i * 16 + lq;
            float v00 = (acc[i][j][0] + b0) * g0, v01 = (acc[i][j][1] + b1) * g1;
            float v10 = (acc[i][j][2] + b0) * g0, v11 = (acc[i][j][3] + b1) * g1;
            if (roundout) {
                v00 = __uint_as_float(f2tf32(v00)); v01 = __uint_as_float(f2tf32(v01));
                v10 = __uint_as_float(f2tf32(v10)); v11 = __uint_as_float(f2tf32(v11));
            }
            *(float2*)(C + (size_t)r0 * N + c0)       = make_float2(v00, v01);
            *(float2*)(C + (size_t)(r0 + 8) * N + c0) = make_float2(v10, v11);
        }
    }
}

// ---------------------------------------------------------------------------
// TF32 tensor-core flash attention.
// BM=64 rows (4 warps x 16), BN=64 keys, DH=128.
// Q A-frags in registers; K/V in smem stride 132; P repacked via shuffles.
// ---------------------------------------------------------------------------
#define KSTRIDE 132
#define FLASH_SMEM_BYTES (2 * 64 * KSTRIDE * 4)

__global__ __launch_bounds__(128) void flash_tf32_kernel(
    const float* __restrict__ Q, const float* __restrict__ K,
    const float* __restrict__ V, const float* __restrict__ spiral,
    float* __restrict__ O)
{
    extern __shared__ float fs[];
    float* sK = fs;                    // [64][132]
    float* sV = fs + 64 * KSTRIDE;     // [64][132]

    const int tid = threadIdx.x;
    const int warp = tid >> 5, lane = tid & 31;
    const int lq = lane >> 2, lr = lane & 3;
    const int qt = blockIdx.x, h = blockIdx.y, b = blockIdx.z;
    const int s0 = qt * 64;
    const float scale = spiral[h] * 0.08838834764831845f;

    const size_t baseQ = ((size_t)b * SEQ + s0) * DIM + (size_t)h * DHEAD;
    const size_t baseK = (size_t)b * SEQ * DIM + (size_t)h * DHEAD;

    // stage Q through sK, then extract A-fragments to registers
    for (int idx = tid; idx < 64 * 32; idx += 128) {
        int r = idx >> 5, c4 = (idx & 31) << 2;
        *(float4*)(sK + r * KSTRIDE + c4) =
            *(const float4*)(Q + baseQ + (size_t)r * DIM + c4);
    }
    __syncthreads();

    unsigned qf[16][4];
    const int qrow = warp * 16 + lq;
#pragma unroll
    for (int ks = 0; ks < 16; ks++) {
        qf[ks][0] = __float_as_uint(sK[qrow * KSTRIDE + ks * 8 + lr]);
        qf[ks][1] = __float_as_uint(sK[(qrow + 8) * KSTRIDE + ks * 8 + lr]);
        qf[ks][2] = __float_as_uint(sK[qrow * KSTRIDE + ks * 8 + lr + 4]);
        qf[ks][3] = __float_as_uint(sK[(qrow + 8) * KSTRIDE + ks * 8 + lr + 4]);
    }
    __syncthreads();

    float o[16][4];
#pragma unroll
    for (int jn = 0; jn < 16; jn++)
#pragma unroll
        for (int t = 0; t < 4; t++) o[jn][t] = 0.f;
    float m0 = -INFINITY, m1 = -INFINITY, l0 = 0.f, l1 = 0.f;

    for (int kt = 0; kt < SEQ / 64; kt++) {
        const size_t kb = baseK + (size_t)kt * 64 * DIM;
        for (int idx = tid; idx < 64 * 32; idx += 128) {
            int r = idx >> 5, c4 = (idx & 31) << 2;
            *(float4*)(sK + r * KSTRIDE + c4) =
                *(const float4*)(K + kb + (size_t)r * DIM + c4);
            *(float4*)(sV + r * KSTRIDE + c4) =
                *(const float4*)(V + kb + (size_t)r * DIM + c4);
        }
        __syncthreads();

        // ---- S = Q @ K^T (64x64), per-warp 16x64 ----
        float sacc[8][4];
#pragma unroll
        for (int j = 0; j < 8; j++)
#pragma unroll
            for (int t = 0; t < 4; t++) sacc[j][t] = 0.f;

#pragma unroll
        for (int ks = 0; ks < 16; ks++) {
#pragma unroll
            for (int j = 0; j < 8; j++) {
                unsigned bf[2];
                bf[0] = __float_as_uint(sK[(j * 8 + lq) * KSTRIDE + ks * 8 + lr]);
                bf[1] = __float_as_uint(sK[(j * 8 + lq) * KSTRIDE + ks * 8 + lr + 4]);
                mma_tf32(sacc[j], qf[ks], bf);
            }
        }

        // ---- online softmax in registers ----
        float mx0 = -INFINITY, mx1 = -INFINITY;
#pragma unroll
        for (int j = 0; j < 8; j++) {
            sacc[j][0] *= scale; sacc[j][1] *= scale;
            sacc[j][2] *= scale; sacc[j][3] *= scale;
            mx0 = fmaxf(mx0, fmaxf(sacc[j][0], sacc[j][1]));
            mx1 = fmaxf(mx1, fmaxf(sacc[j][2], sacc[j][3]));
        }
        mx0 = fmaxf(mx0, __shfl_xor_sync(0xffffffffu, mx0, 1));
        mx0 = fmaxf(mx0, __shfl_xor_sync(0xffffffffu, mx0, 2));
        mx1 = fmaxf(mx1, __shfl_xor_sync(0xffffffffu, mx1, 1));
        mx1 = fmaxf(mx1, __shfl_xor_sync(0xffffffffu, mx1, 2));

        float mn0 = fmaxf(m0, mx0), mn1 = fmaxf(m1, mx1);
        float al0 = __expf(m0 - mn0), al1 = __expf(m1 - mn1);
        m0 = mn0; m1 = mn1;

        unsigned pb[8][4];
        float sum0 = 0.f, sum1 = 0.f;
#pragma unroll
        for (int j = 0; j < 8; j++) {
            float p0 = __expf(sacc[j][0] - mn0);
            float p1 = __expf(sacc[j][1] - mn0);
            float p2 = __expf(sacc[j][2] - mn1);
            float p3 = __expf(sacc[j][3] - mn1);
            sum0 += p0 + p1; sum1 += p2 + p3;
            pb[j][0] = f2tf32(p0); pb[j][1] = f2tf32(p1);
            pb[j][2] = f2tf32(p2); pb[j][3] = f2tf32(p3);
        }
        sum0 += __shfl_xor_sync(0xffffffffu, sum0, 1);
        sum0 += __shfl_xor_sync(0xffffffffu, sum0, 2);
        sum1 += __shfl_xor_sync(0xffffffffu, sum1, 1);
        sum1 += __shfl_xor_sync(0xffffffffu, sum1, 2);
        l0 = l0 * al0 + sum0;
        l1 = l1 * al1 + sum1;

#pragma unroll
        for (int jn = 0; jn < 16; jn++) {
            o[jn][0] *= al0; o[jn][1] *= al0;
            o[jn][2] *= al1; o[jn][3] *= al1;
        }

        // ---- O += P @ V ----
        const int srcl = lq * 4 + (lr >> 1);
#pragma unroll
        for (int k8 = 0; k8 < 8; k8++) {
            unsigned a[4];
            unsigned t00 = __shfl_sync(0xffffffffu, pb[k8][0], srcl);
            unsigned t01 = __shfl_sync(0xffffffffu, pb[k8][1], srcl);
            unsigned t10 = __shfl_sync(0xffffffffu, pb[k8][2], srcl);
            unsigned t11 = __shfl_sync(0xffffffffu, pb[k8][3], srcl);
            unsigned u00 = __shfl_sync(0xffffffffu, pb[k8][0], srcl + 2);
            unsigned u01 = __shfl_sync(0xffffffffu, pb[k8][1], srcl + 2);
            unsigned u10 = __shfl_sync(0xffffffffu, pb[k8][2], srcl + 2);
            unsigned u11 = __shfl_sync(0xffffffffu, pb[k8][3], srcl + 2);
            a[0] = (lr & 1) ? t01 : t00;
            a[1] = (lr & 1) ? t11 : t10;
            a[2] = (lr & 1) ? u01 : u00;
            a[3] = (lr & 1) ? u11 : u10;
#pragma unroll
            for (int jn = 0; jn < 16; jn++) {
                unsigned bf[2];
                bf[0] = __float_as_uint(sV[(k8 * 8 + lr) * KSTRIDE + jn * 8 + lq]);
                bf[1] = __float_as_uint(sV[(k8 * 8 + lr + 4) * KSTRIDE + jn * 8 + lq]);
                mma_tf32(o[jn], a, bf);
            }
        }
        __syncthreads();
    }

    // finalize + store (C-frag layout)
    const float inv0 = 1.0f / l0, inv1 = 1.0f / l1;
    float* Orow0 = O + baseQ + (size_t)qrow * DIM;
    float* Orow1 = O + baseQ + (size_t)(qrow + 8) * DIM;
#pragma unroll
    for (int jn = 0; jn < 16; jn++) {
        int c = jn * 8 + 2 * lr;
        *(float2*)(Orow0 + c) = make_float2(o[jn][0] * inv0, o[jn][1] * inv0);
        *(float2*)(Orow1 + c) = make_float2(o[jn][2] * inv1, o[jn][3] * inv1);
    }
}

// ---------------------------------------------------------------------------
extern "C" void kernel_launch(void* const* d_in, const int* in_sizes, int n_in,
                              void* d_out, int out_size)
{
    const float* x      = (const float*)d_in[0];
    const float* Wq     = (const float*)d_in[1];
    const float* bq     = (const float*)d_in[2];
    const float* Wk     = (const float*)d_in[3];
    const float* bk     = (const float*)d_in[4];
    const float* Wv     = (const float*)d_in[5];
    const float* bv     = (const float*)d_in[6];
    const float* Wo     = (const float*)d_in[7];
    const float* bo     = (const float*)d_in[8];
    const float* spiral = (const float*)d_in[9];
    const float* rot    = (const float*)d_in[10];
    float* out = (float*)d_out;

    float *Qp, *Kp, *Vp, *Ap;
    cudaGetSymbolAddress((void**)&Qp, g_Q);
    cudaGetSymbolAddress((void**)&Kp, g_K);
    cudaGetSymbolAddress((void**)&Vp, g_V);
    cudaGetSymbolAddress((void**)&Ap, g_A);

    const int M = BATCH * SEQ;                  // 8192
    dim3 gg(DIM / GBN, M / GBM);                // 16 x 64

    cudaFuncSetAttribute(gemm_tf32_kernel,
                         cudaFuncAttributeMaxDynamicSharedMemorySize, GEMM_SMEM_BYTES);

    gemm_tf32_kernel<<<gg, 256, GEMM_SMEM_BYTES>>>(x, Wq, bq, rot, 1, 1, Qp, M, DIM, DIM);
    gemm_tf32_kernel<<<gg, 256, GEMM_SMEM_BYTES>>>(x, Wk, bk, rot, 2, 1, Kp, M, DIM, DIM);
    gemm_tf32_kernel<<<gg, 256, GEMM_SMEM_BYTES>>>(x, Wv, bv, nullptr, 0, 1, Vp, M, DIM, DIM);

    cudaFuncSetAttribute(flash_tf32_kernel,
                         cudaFuncAttributeMaxDynamicSharedMemorySize, FLASH_SMEM_BYTES);
    flash_tf32_kernel<<<dim3(SEQ / 64, NH, BATCH), 128, FLASH_SMEM_BYTES>>>(
        Qp, Kp, Vp, spiral, Ap);

    gemm_tf32_kernel<<<gg, 256, GEMM_SMEM_BYTES>>>(Ap, Wo, bo, nullptr, 0, 0, out, M, DIM, DIM);
}

// round 6
// speedup vs baseline: 5.3449x; 1.0044x over previous
#include <cuda_runtime.h>
#include <math.h>

#define BATCH 4
#define SEQ   2048
#define DIM   2048
#define NH    16
#define DHEAD 128

__device__ float g_Q[BATCH * SEQ * DIM];
__device__ float g_K[BATCH * SEQ * DIM];
__device__ float g_V[BATCH * SEQ * DIM];
__device__ float g_A[BATCH * SEQ * DIM];

__device__ __forceinline__ unsigned f2tf32(float x) {
    unsigned u;
    asm("cvt.rna.tf32.f32 %0, %1;" : "=r"(u) : "f"(x));
    return u;
}

__device__ __forceinline__ void mma_tf32(float* d, const unsigned* a, const unsigned* b) {
    asm volatile(
        "mma.sync.aligned.m16n8k8.row.col.f32.tf32.tf32.f32 "
        "{%0,%1,%2,%3}, {%4,%5,%6,%7}, {%8,%9}, {%0,%1,%2,%3};\n"
        : "+f"(d[0]), "+f"(d[1]), "+f"(d[2]), "+f"(d[3])
        : "r"(a[0]), "r"(a[1]), "r"(a[2]), "r"(a[3]), "r"(b[0]), "r"(b[1]));
}

// ---------------------------------------------------------------------------
// TF32 NT GEMM: C = (A @ W^T + bias) * gate, optional tf32 rounding of output
// ---------------------------------------------------------------------------
#define GBM 128
#define GBN 128
#define GBK 32
#define GSTRIDE 36
#define GBUF (128 * GSTRIDE)
#define GEMM_SMEM_BYTES (4 * GBUF * 4)

__global__ __launch_bounds__(256) void gemm_tf32_kernel(
    const float* __restrict__ A, const float* __restrict__ W,
    const float* __restrict__ bias, const float* __restrict__ rot,
    int mode, int roundout, float* __restrict__ C, int M, int N, int K)
{
    extern __shared__ unsigned sm[];
    unsigned* As = sm;
    unsigned* Bs = sm + 2 * GBUF;

    const int tid = threadIdx.x;
    const int warp = tid >> 5, lane = tid & 31;
    const int wm = (warp >> 2) * 64;
    const int wn = (warp & 3) * 32;
    const int bm = blockIdx.y * GBM, bn = blockIdx.x * GBN;

    const int lrow = tid >> 3;
    const int lcol = (tid & 7) * 4;

    float acc[4][4][4];
#pragma unroll
    for (int i = 0; i < 4; i++)
#pragma unroll
        for (int j = 0; j < 4; j++)
#pragma unroll
            for (int t = 0; t < 4; t++) acc[i][j][t] = 0.f;

    const float* Ag = A + (size_t)(bm + lrow) * K + lcol;
    const float* Wg = W + (size_t)(bn + lrow) * K + lcol;

    float4 ra[4], rb[4];

    auto G2R = [&](int kt) {
        const size_t ko = (size_t)kt * GBK;
#pragma unroll
        for (int it = 0; it < 4; it++) {
            ra[it] = *(const float4*)(Ag + (size_t)it * 32 * K + ko);
            rb[it] = *(const float4*)(Wg + (size_t)it * 32 * K + ko);
        }
    };
    auto R2S = [&](int buf) {
#pragma unroll
        for (int it = 0; it < 4; it++) {
            int base = buf * GBUF + (lrow + it * 32) * GSTRIDE + lcol;
            uint4 ua = make_uint4(f2tf32(ra[it].x), f2tf32(ra[it].y),
                                  f2tf32(ra[it].z), f2tf32(ra[it].w));
            uint4 ub = make_uint4(f2tf32(rb[it].x), f2tf32(rb[it].y),
                                  f2tf32(rb[it].z), f2tf32(rb[it].w));
            *(uint4*)(As + base) = ua;
            *(uint4*)(Bs + base) = ub;
        }
    };

    const int ntiles = K / GBK;
    G2R(0);
    R2S(0);
    __syncthreads();

    const int lq = lane >> 2;
    const int lr = lane & 3;

    for (int kt = 0; kt < ntiles; kt++) {
        if (kt + 1 < ntiles) G2R(kt + 1);

        const unsigned* Ab = As + (kt & 1) * GBUF;
        const unsigned* Bb = Bs + (kt & 1) * GBUF;
#pragma unroll
        for (int k8 = 0; k8 < 4; k8++) {
            const int kc = k8 * 8 + lr;
            unsigned af[4][4], bf[4][2];
#pragma unroll
            for (int i = 0; i < 4; i++) {
                int r = wm + i * 16 + lq;
                af[i][0] = Ab[r * GSTRIDE + kc];
                af[i][1] = Ab[(r + 8) * GSTRIDE + kc];
                af[i][2] = Ab[r * GSTRIDE + kc + 4];
                af[i][3] = Ab[(r + 8) * GSTRIDE + kc + 4];
            }
#pragma unroll
            for (int j = 0; j < 4; j++) {
                int c = wn + j * 8 + lq;
                bf[j][0] = Bb[c * GSTRIDE + kc];
                bf[j][1] = Bb[c * GSTRIDE + kc + 4];
            }
#pragma unroll
            for (int i = 0; i < 4; i++)
#pragma unroll
                for (int j = 0; j < 4; j++)
                    mma_tf32(acc[i][j], af[i], bf[j]);
        }

        if (kt + 1 < ntiles) R2S((kt + 1) & 1);
        __syncthreads();
    }

#pragma unroll
    for (int j = 0; j < 4; j++) {
        int c0 = bn + wn + j * 8 + (lr << 1);
        float b0 = __ldg(bias + c0), b1 = __ldg(bias + c0 + 1);
        float g0 = 1.f, g1 = 1.f;
        if (mode == 1) { g0 = cosf(__ldg(rot + c0)); g1 = cosf(__ldg(rot + c0 + 1)); }
        else if (mode == 2) { g0 = sinf(__ldg(rot + c0)); g1 = sinf(__ldg(rot + c0 + 1)); }
#pragma unroll
        for (int i = 0; i < 4; i++) {
            int r0 = bm + wm + i * 16 + lq;
            float v00 = (acc[i][j][0] + b0) * g0, v01 = (acc[i][j][1] + b1) * g1;
            float v10 = (acc[i][j][2] + b0) * g0, v11 = (acc[i][j][3] + b1) * g1;
            if (roundout) {
                v00 = __uint_as_float(f2tf32(v00)); v01 = __uint_as_float(f2tf32(v01));
                v10 = __uint_as_float(f2tf32(v10)); v11 = __uint_as_float(f2tf32(v11));
            }
            *(float2*)(C + (size_t)r0 * N + c0)       = make_float2(v00, v01);
            *(float2*)(C + (size_t)(r0 + 8) * N + c0) = make_float2(v10, v11);
        }
    }
}

// ---------------------------------------------------------------------------
// TF32 tensor-core flash attention.
// BM=64 rows (4 warps x 16), BN=64 keys, DH=128.
// Q A-frags in registers; K/V in smem stride 132; P repacked via shuffles.
// ---------------------------------------------------------------------------
#define KSTRIDE 132
#define FLASH_SMEM_BYTES (2 * 64 * KSTRIDE * 4)

__global__ __launch_bounds__(128) void flash_tf32_kernel(
    const float* __restrict__ Q, const float* __restrict__ K,
    const float* __restrict__ V, const float* __restrict__ spiral,
    float* __restrict__ O)
{
    extern __shared__ float fs[];
    float* sK = fs;                    // [64][132]
    float* sV = fs + 64 * KSTRIDE;     // [64][132]

    const int tid = threadIdx.x;
    const int warp = tid >> 5, lane = tid & 31;
    const int lq = lane >> 2, lr = lane & 3;
    const int qt = blockIdx.x, h = blockIdx.y, b = blockIdx.z;
    const int s0 = qt * 64;
    const float scale = spiral[h] * 0.08838834764831845f;

    const size_t baseQ = ((size_t)b * SEQ + s0) * DIM + (size_t)h * DHEAD;
    const size_t baseK = (size_t)b * SEQ * DIM + (size_t)h * DHEAD;

    // stage Q through sK, then extract A-fragments to registers
    for (int idx = tid; idx < 64 * 32; idx += 128) {
        int r = idx >> 5, c4 = (idx & 31) << 2;
        *(float4*)(sK + r * KSTRIDE + c4) =
            *(const float4*)(Q + baseQ + (size_t)r * DIM + c4);
    }
    __syncthreads();

    unsigned qf[16][4];
    const int qrow = warp * 16 + lq;
#pragma unroll
    for (int ks = 0; ks < 16; ks++) {
        qf[ks][0] = __float_as_uint(sK[qrow * KSTRIDE + ks * 8 + lr]);
        qf[ks][1] = __float_as_uint(sK[(qrow + 8) * KSTRIDE + ks * 8 + lr]);
        qf[ks][2] = __float_as_uint(sK[qrow * KSTRIDE + ks * 8 + lr + 4]);
        qf[ks][3] = __float_as_uint(sK[(qrow + 8) * KSTRIDE + ks * 8 + lr + 4]);
    }
    __syncthreads();

    float o[16][4];
#pragma unroll
    for (int jn = 0; jn < 16; jn++)
#pragma unroll
        for (int t = 0; t < 4; t++) o[jn][t] = 0.f;
    float m0 = -INFINITY, m1 = -INFINITY, l0 = 0.f, l1 = 0.f;

    for (int kt = 0; kt < SEQ / 64; kt++) {
        const size_t kb = baseK + (size_t)kt * 64 * DIM;
        for (int idx = tid; idx < 64 * 32; idx += 128) {
            int r = idx >> 5, c4 = (idx & 31) << 2;
            *(float4*)(sK + r * KSTRIDE + c4) =
                *(const float4*)(K + kb + (size_t)r * DIM + c4);
            *(float4*)(sV + r * KSTRIDE + c4) =
                *(const float4*)(V + kb + (size_t)r * DIM + c4);
        }
        __syncthreads();

        // ---- S = Q @ K^T (64x64), per-warp 16x64 ----
        float sacc[8][4];
#pragma unroll
        for (int j = 0; j < 8; j++)
#pragma unroll
            for (int t = 0; t < 4; t++) sacc[j][t] = 0.f;

#pragma unroll
        for (int ks = 0; ks < 16; ks++) {
#pragma unroll
            for (int j = 0; j < 8; j++) {
                unsigned bf[2];
                bf[0] = __float_as_uint(sK[(j * 8 + lq) * KSTRIDE + ks * 8 + lr]);
                bf[1] = __float_as_uint(sK[(j * 8 + lq) * KSTRIDE + ks * 8 + lr + 4]);
                mma_tf32(sacc[j], qf[ks], bf);
            }
        }

        // ---- online softmax in registers ----
        float mx0 = -INFINITY, mx1 = -INFINITY;
#pragma unroll
        for (int j = 0; j < 8; j++) {
            sacc[j][0] *= scale; sacc[j][1] *= scale;
            sacc[j][2] *= scale; sacc[j][3] *= scale;
            mx0 = fmaxf(mx0, fmaxf(sacc[j][0], sacc[j][1]));
            mx1 = fmaxf(mx1, fmaxf(sacc[j][2], sacc[j][3]));
        }
        mx0 = fmaxf(mx0, __shfl_xor_sync(0xffffffffu, mx0, 1));
        mx0 = fmaxf(mx0, __shfl_xor_sync(0xffffffffu, mx0, 2));
        mx1 = fmaxf(mx1, __shfl_xor_sync(0xffffffffu, mx1, 1));
        mx1 = fmaxf(mx1, __shfl_xor_sync(0xffffffffu, mx1, 2));

        float mn0 = fmaxf(m0, mx0), mn1 = fmaxf(m1, mx1);
        float al0 = __expf(m0 - mn0), al1 = __expf(m1 - mn1);
        m0 = mn0; m1 = mn1;

        unsigned pb[8][4];
        float sum0 = 0.f, sum1 = 0.f;
#pragma unroll
        for (int j = 0; j < 8; j++) {
            float p0 = __expf(sacc[j][0] - mn0);
            float p1 = __expf(sacc[j][1] - mn0);
            float p2 = __expf(sacc[j][2] - mn1);
            float p3 = __expf(sacc[j][3] - mn1);
            sum0 += p0 + p1; sum1 += p2 + p3;
            pb[j][0] = f2tf32(p0); pb[j][1] = f2tf32(p1);
            pb[j][2] = f2tf32(p2); pb[j][3] = f2tf32(p3);
        }
        sum0 += __shfl_xor_sync(0xffffffffu, sum0, 1);
        sum0 += __shfl_xor_sync(0xffffffffu, sum0, 2);
        sum1 += __shfl_xor_sync(0xffffffffu, sum1, 1);
        sum1 += __shfl_xor_sync(0xffffffffu, sum1, 2);
        l0 = l0 * al0 + sum0;
        l1 = l1 * al1 + sum1;

#pragma unroll
        for (int jn = 0; jn < 16; jn++) {
            o[jn][0] *= al0; o[jn][1] *= al0;
            o[jn][2] *= al1; o[jn][3] *= al1;
        }

        // ---- O += P @ V ----
        const int srcl = lq * 4 + (lr >> 1);
#pragma unroll
        for (int k8 = 0; k8 < 8; k8++) {
            unsigned a[4];
            unsigned t00 = __shfl_sync(0xffffffffu, pb[k8][0], srcl);
            unsigned t01 = __shfl_sync(0xffffffffu, pb[k8][1], srcl);
            unsigned t10 = __shfl_sync(0xffffffffu, pb[k8][2], srcl);
            unsigned t11 = __shfl_sync(0xffffffffu, pb[k8][3], srcl);
            unsigned u00 = __shfl_sync(0xffffffffu, pb[k8][0], srcl + 2);
            unsigned u01 = __shfl_sync(0xffffffffu, pb[k8][1], srcl + 2);
            unsigned u10 = __shfl_sync(0xffffffffu, pb[k8][2], srcl + 2);
            unsigned u11 = __shfl_sync(0xffffffffu, pb[k8][3], srcl + 2);
            a[0] = (lr & 1) ? t01 : t00;
            a[1] = (lr & 1) ? t11 : t10;
            a[2] = (lr & 1) ? u01 : u00;
            a[3] = (lr & 1) ? u11 : u10;
#pragma unroll
            for (int jn = 0; jn < 16; jn++) {
                unsigned bf[2];
                bf[0] = __float_as_uint(sV[(k8 * 8 + lr) * KSTRIDE + jn * 8 + lq]);
                bf[1] = __float_as_uint(sV[(k8 * 8 + lr + 4) * KSTRIDE + jn * 8 + lq]);
                mma_tf32(o[jn], a, bf);
            }
        }
        __syncthreads();
    }

    // finalize + store (C-frag layout)
    const float inv0 = 1.0f / l0, inv1 = 1.0f / l1;
    float* Orow0 = O + baseQ + (size_t)qrow * DIM;
    float* Orow1 = O + baseQ + (size_t)(qrow + 8) * DIM;
#pragma unroll
    for (int jn = 0; jn < 16; jn++) {
        int c = jn * 8 + 2 * lr;
        *(float2*)(Orow0 + c) = make_float2(o[jn][0] * inv0, o[jn][1] * inv0);
        *(float2*)(Orow1 + c) = make_float2(o[jn][2] * inv1, o[jn][3] * inv1);
    }
}

// ---------------------------------------------------------------------------
extern "C" void kernel_launch(void* const* d_in, const int* in_sizes, int n_in,
                              void* d_out, int out_size)
{
    const float* x      = (const float*)d_in[0];
    const float* Wq     = (const float*)d_in[1];
    const float* bq     = (const float*)d_in[2];
    const float* Wk     = (const float*)d_in[3];
    const float* bk     = (const float*)d_in[4];
    const float* Wv     = (const float*)d_in[5];
    const float* bv     = (const float*)d_in[6];
    const float* Wo     = (const float*)d_in[7];
    const float* bo     = (const float*)d_in[8];
    const float* spiral = (const float*)d_in[9];
    const float* rot    = (const float*)d_in[10];
    float* out = (float*)d_out;

    float *Qp, *Kp, *Vp, *Ap;
    cudaGetSymbolAddress((void**)&Qp, g_Q);
    cudaGetSymbolAddress((void**)&Kp, g_K);
    cudaGetSymbolAddress((void**)&Vp, g_V);
    cudaGetSymbolAddress((void**)&Ap, g_A);

    const int M = BATCH * SEQ;                  // 8192
    dim3 gg(DIM / GBN, M / GBM);                // 16 x 64

    cudaFuncSetAttribute(gemm_tf32_kernel,
                         cudaFuncAttributeMaxDynamicSharedMemorySize, GEMM_SMEM_BYTES);

    gemm_tf32_kernel<<<gg, 256, GEMM_SMEM_BYTES>>>(x, Wq, bq, rot, 1, 1, Qp, M, DIM, DIM);
    gemm_tf32_kernel<<<gg, 256, GEMM_SMEM_BYTES>>>(x, Wk, bk, rot, 2, 1, Kp, M, DIM, DIM);
    gemm_tf32_kernel<<<gg, 256, GEMM_SMEM_BYTES>>>(x, Wv, bv, nullptr, 0, 1, Vp, M, DIM, DIM);

    cudaFuncSetAttribute(flash_tf32_kernel,
                         cudaFuncAttributeMaxDynamicSharedMemorySize, FLASH_SMEM_BYTES);
    flash_tf32_kernel<<<dim3(SEQ / 64, NH, BATCH), 128, FLASH_SMEM_BYTES>>>(
        Qp, Kp, Vp, spiral, Ap);

    gemm_tf32_kernel<<<gg, 256, GEMM_SMEM_BYTES>>>(Ap, Wo, bo, nullptr, 0, 0, out, M, DIM, DIM);
}